// round 17
// baseline (speedup 1.0000x reference)
#include <cuda_runtime.h>
#include <cuda_pipeline.h>
#include <math.h>
#include <mma.h>

using namespace nvcuda;

// Problem constants
#define NNODES 10000
#define NEDGES 160000
#define DFEAT  512
#define DOUT   256

#define XN4 (NNODES * DFEAT / 4)
#define WN4 (DFEAT * DFEAT / 4)
#define CN4 (3 * DFEAT * DOUT / 4)

// ---------------- scratch (no allocations allowed) ----------------
__device__ __align__(16) float g_bufA[NNODES * DFEAT];
__device__ __align__(16) float g_bufB[NNODES * DFEAT];
__device__ __align__(16) float g_bufC[NNODES * DFEAT];
__device__ __align__(16) float g_w12[2 * DFEAT * DFEAT];   // tf32(W1), tf32(W2)
__device__ __align__(16) float g_wc [3 * DFEAT * DOUT];    // tf32(Wc) as [1536,256]
__device__ __align__(16) float g_dinv [NNODES];
__device__ __align__(16) float g_self [NNODES];
__device__ __align__(16) float g_dinvC[NNODES];
__device__ __align__(16) int   g_cnt[NNODES];
__device__ __align__(16) int   g_off[NNODES + 1];
__device__ __align__(16) int   g_ins[NNODES];
__device__ __align__(16) int   g_row[NEDGES];
__device__ __align__(16) int   g_col[NEDGES];
__device__ __align__(16) char  g_ok [NEDGES];
__device__ __align__(16) int   g_rowS [NEDGES];
__device__ __align__(16) float g_normS[NEDGES];
__device__ __align__(16) float g_normCS[NEDGES];
__device__ int g_is64;

template<int S>
__device__ __forceinline__ float* buf() {
    if constexpr (S == 0) return g_bufA;
    else if constexpr (S == 1) return g_bufB;
    else return g_bufC;
}

__device__ __forceinline__ float celuf(float x) {
    return x > 0.0f ? x : expm1f(x);
}

// ---------------- GEMM smem geometry (3-stage, BK=32) ----------------
#define ALD 36                       // As row: 32 floats + 4 pad
#define BLD 132                      // Bs row: 128 floats + 4 pad
#define SLD 20                       // epilogue staging ldm (mult of 4)
#define AS_ELEMS (3 * 128 * ALD)     // 13824 floats
#define BS_ELEMS (3 * 32 * BLD)      // 12672 floats
#define SMEM_DYN ((AS_ELEMS + BS_ELEMS) * 4)   // 105984 bytes

// forward decl for attribute setup
template<int ASEL, int BOFF> __global__ void k_tgemm();
__global__ void k_cgemm(const float*, float*);

static void setup_attrs() {
    cudaFuncSetAttribute((const void*)k_tgemm<2, 0>,
                         cudaFuncAttributeMaxDynamicSharedMemorySize, SMEM_DYN);
    cudaFuncSetAttribute((const void*)k_tgemm<1, DFEAT * DFEAT>,
                         cudaFuncAttributeMaxDynamicSharedMemorySize, SMEM_DYN);
    cudaFuncSetAttribute((const void*)k_cgemm,
                         cudaFuncAttributeMaxDynamicSharedMemorySize, SMEM_DYN);
}

namespace {
struct EagerLoad {
    EagerLoad() {
        void* p = nullptr;
        cudaGetSymbolAddress(&p, g_bufA);   // eager module load
        (void)p;
        setup_attrs();
    }
};
static EagerLoad _eager_load_instance;
}

// ---------------- init + dtype probe (merged) ----------------
__global__ void k_init(const int* __restrict__ ei32) {
    int i = blockIdx.x * blockDim.x + threadIdx.x;
    if (i < NNODES) { g_dinv[i] = 1.0f; g_dinvC[i] = 0.0f; g_cnt[i] = 0; }
    if (blockIdx.x == 0) {
        __shared__ int any;
        if (threadIdx.x == 0) any = 0;
        __syncthreads();
        if (ei32[2 * threadIdx.x + 1] != 0) atomicOr(&any, 1);
        __syncthreads();
        if (threadIdx.x == 0) g_is64 = (any == 0) ? 1 : 0;
    }
}

// ---------------- merged tf32 pre-conversion ----------------
__global__ void k_cvtall(const float* __restrict__ x,  const float* __restrict__ W1,
                         const float* __restrict__ W2, const float* __restrict__ Wc) {
    int i = blockIdx.x * blockDim.x + threadIdx.x;
    const float4* src; float4* dst; int off;
    if (i < XN4)                  { src = (const float4*)x;  dst = (float4*)g_bufC;        off = i; }
    else if (i < XN4 + WN4)       { src = (const float4*)W1; dst = (float4*)g_w12;         off = i - XN4; }
    else if (i < XN4 + 2 * WN4)   { src = (const float4*)W2; dst = (float4*)g_w12 + WN4;   off = i - XN4 - WN4; }
    else if (i < XN4 + 2 * WN4 + CN4) { src = (const float4*)Wc; dst = (float4*)g_wc;      off = i - XN4 - 2 * WN4; }
    else return;
    float4 v = src[off];
    float4 o;
    o.x = wmma::__float_to_tf32(v.x);
    o.y = wmma::__float_to_tf32(v.y);
    o.z = wmma::__float_to_tf32(v.z);
    o.w = wmma::__float_to_tf32(v.w);
    dst[off] = o;
}

// ---------------- edge preprocessing ----------------
__global__ void k_edge1(const int* __restrict__ ei32, const float* __restrict__ w) {
    int e = blockIdx.x * blockDim.x + threadIdx.x;
    if (e >= NEDGES) return;
    int r, c;
    if (g_is64) {
        r = ei32[2 * e];
        c = ei32[2 * (NEDGES + e)];
    } else {
        r = ei32[e];
        c = ei32[NEDGES + e];
    }
    bool ok = ((unsigned)r < NNODES) && ((unsigned)c < NNODES);
    if (!ok) { r = 0; c = 0; }
    g_row[e] = r; g_col[e] = c; g_ok[e] = ok ? 1 : 0;
    if (ok) {
        float we = w[e];
        atomicAdd(&g_dinv[c], we);
        if (r != c) atomicAdd(&g_dinvC[r], we);
    }
    atomicAdd(&g_cnt[c], 1);
}

// hierarchical exclusive scan of g_cnt -> g_off/g_ins
__global__ void k_scan() {
    __shared__ int wsum[32];
    int t = threadIdx.x;
    int lane = t & 31, wi = t >> 5;
    const int CH = (NNODES + 1023) / 1024;
    int lo = t * CH, hi = min(lo + CH, NNODES);
    int s = 0;
    for (int i = lo; i < hi; i++) s += g_cnt[i];
    int v = s;
    #pragma unroll
    for (int d = 1; d < 32; d <<= 1) {
        int n = __shfl_up_sync(0xFFFFFFFFu, v, d);
        if (lane >= d) v += n;
    }
    if (lane == 31) wsum[wi] = v;
    __syncthreads();
    if (wi == 0) {
        int w = wsum[lane];
        #pragma unroll
        for (int d = 1; d < 32; d <<= 1) {
            int n = __shfl_up_sync(0xFFFFFFFFu, w, d);
            if (lane >= d) w += n;
        }
        wsum[lane] = w;
    }
    __syncthreads();
    int excl = (v - s) + (wi > 0 ? wsum[wi - 1] : 0);
    int run = excl;
    for (int i = lo; i < hi; i++) {
        g_off[i] = run; g_ins[i] = run; run += g_cnt[i];
    }
    if (t == 0) g_off[NNODES] = wsum[31];
}

__global__ void k_dinv() {
    int i = blockIdx.x * blockDim.x + threadIdx.x;
    if (i >= NNODES) return;
    float d  = g_dinv[i];
    float di = rsqrtf(d);
    g_dinv[i] = di;
    g_self[i] = di * di;
    float dc = g_dinvC[i];
    g_dinvC[i] = (dc > 0.0f) ? rsqrtf(dc) : 0.0f;
}

__global__ void k_edge2(const float* __restrict__ w) {
    int e = blockIdx.x * blockDim.x + threadIdx.x;
    if (e >= NEDGES) return;
    int r = g_row[e], c = g_col[e];
    float we = g_ok[e] ? w[e] : 0.0f;
    float nv  = g_dinv[r] * we * g_dinv[c];
    float w0  = (r == c) ? 0.0f : we;
    float nvc = g_dinvC[r] * w0 * g_dinvC[c];
    int pos = atomicAdd(&g_ins[c], 1);
    g_rowS[pos]   = r;
    g_normS[pos]  = nv;
    g_normCS[pos] = nvc;
}

// ---------------- SpMM (gather by dest-CSR), unroll 8/4/1 ----------------
// MODE 0: GCN : dst = tf32(celu(sum norm*src[row] + self*src[c] + bias))
// MODE 1: lhat: dst = tf32(-sum normC*src[row])
// MODE 2: Tx2 : dst = tf32(-2*sum normC*src[row] - sub[c])
template<int MODE, int SRC, int DST, int SUB>
__global__ void __launch_bounds__(128)
k_spmm(const float* __restrict__ bias) {
    const float* src = buf<SRC>();
    float*       dst = buf<DST>();
    int c = blockIdx.x;
    int t = threadIdx.x;
    int beg = g_off[c], end = g_off[c + 1];
    float4 acc = make_float4(0.f, 0.f, 0.f, 0.f);
    int k = beg;
    for (; k + 7 < end; k += 8) {
        float nv[8]; int rr[8];
        #pragma unroll
        for (int u = 0; u < 8; u++) {
            nv[u] = (MODE == 0) ? g_normS[k + u] : g_normCS[k + u];
            rr[u] = g_rowS[k + u];
        }
        #pragma unroll
        for (int u = 0; u < 8; u++) {
            float4 s = ((const float4*)(src + rr[u] * DFEAT))[t];
            acc.x += nv[u] * s.x; acc.y += nv[u] * s.y;
            acc.z += nv[u] * s.z; acc.w += nv[u] * s.w;
        }
    }
    for (; k + 3 < end; k += 4) {
        float nv[4]; int rr[4];
        #pragma unroll
        for (int u = 0; u < 4; u++) {
            nv[u] = (MODE == 0) ? g_normS[k + u] : g_normCS[k + u];
            rr[u] = g_rowS[k + u];
        }
        #pragma unroll
        for (int u = 0; u < 4; u++) {
            float4 s = ((const float4*)(src + rr[u] * DFEAT))[t];
            acc.x += nv[u] * s.x; acc.y += nv[u] * s.y;
            acc.z += nv[u] * s.z; acc.w += nv[u] * s.w;
        }
    }
    for (; k < end; k++) {
        float nv = (MODE == 0) ? g_normS[k] : g_normCS[k];
        int r = g_rowS[k];
        float4 s = ((const float4*)(src + r * DFEAT))[t];
        acc.x += nv * s.x; acc.y += nv * s.y; acc.z += nv * s.z; acc.w += nv * s.w;
    }
    if (MODE == 0) {
        float sn = g_self[c];
        float4 s = ((const float4*)(src + c * DFEAT))[t];
        float4 b = ((const float4*)bias)[t];
        acc.x = wmma::__float_to_tf32(celuf(acc.x + sn * s.x + b.x));
        acc.y = wmma::__float_to_tf32(celuf(acc.y + sn * s.y + b.y));
        acc.z = wmma::__float_to_tf32(celuf(acc.z + sn * s.z + b.z));
        acc.w = wmma::__float_to_tf32(celuf(acc.w + sn * s.w + b.w));
    } else if (MODE == 1) {
        acc.x = wmma::__float_to_tf32(-acc.x);
        acc.y = wmma::__float_to_tf32(-acc.y);
        acc.z = wmma::__float_to_tf32(-acc.z);
        acc.w = wmma::__float_to_tf32(-acc.w);
    } else {
        const float* sub = buf<SUB>();
        float4 sb = ((const float4*)(sub + c * DFEAT))[t];
        acc.x = wmma::__float_to_tf32(-2.f * acc.x - sb.x);
        acc.y = wmma::__float_to_tf32(-2.f * acc.y - sb.y);
        acc.z = wmma::__float_to_tf32(-2.f * acc.z - sb.z);
        acc.w = wmma::__float_to_tf32(-2.f * acc.w - sb.w);
    }
    ((float4*)(dst + c * DFEAT))[t] = acc;
}

// ---------------- TF32 GEMM: BK=32, 3-stage cp.async, dynamic smem -------------
// 128x128 tile, 256 threads (8 warps as 2x4), wmma m16n16k8, tf32 pre-rounded inputs.

// GCN GEMM: g_bufA = buf<ASEL> @ tf32W(g_w12+BOFF).  M=NNODES, N=K=512.
template<int ASEL, int BOFF>
__global__ void __launch_bounds__(256, 2)
k_tgemm() {
    constexpr int M = NNODES, N = DFEAT, K = DFEAT;
    constexpr int NT = K / 32;    // 16

    const float* A  = buf<ASEL>();
    const float* Bw = g_w12 + BOFF;
    float*       C  = g_bufA;

    extern __shared__ float dsm[];
    float (*As)[128][ALD] = (float(*)[128][ALD])dsm;
    float (*Bs)[32][BLD]  = (float(*)[32][BLD])(dsm + AS_ELEMS);

    int tid = threadIdx.x;
    int wid = tid >> 5;
    int warp_m = wid >> 2;
    int warp_n = wid & 3;
    int mBase = blockIdx.x * 128;
    int nBase = blockIdx.y * 128;

    wmma::fragment<wmma::accumulator, 16, 16, 8, float> cf[4][2];
    #pragma unroll
    for (int mi = 0; mi < 4; mi++)
        #pragma unroll
        for (int ni = 0; ni < 2; ni++)
            wmma::fill_fragment(cf[mi][ni], 0.0f);

    int ar = tid >> 1;            // A row 0..127
    int aslot = (tid & 1) * 4;    // float4 slots 0..7, this thread does aslot..aslot+3
    int br = tid >> 3;            // B row 0..31
    int bslot = (tid & 7) * 4;    // float4 slots 0..31, this thread does bslot..bslot+3

    bool aValid = (mBase + ar) < M;
    const float* aRowPtr = A + (size_t)(mBase + ar) * K;

    auto issue = [&](int kt, int bsel) {
        int k0 = kt * 32;
        #pragma unroll
        for (int j = 0; j < 4; j++) {
            if (aValid)
                __pipeline_memcpy_async(&As[bsel][ar][(aslot + j) * 4],
                                        aRowPtr + k0 + (aslot + j) * 4, 16);
            else
                *(float4*)&As[bsel][ar][(aslot + j) * 4] = make_float4(0.f, 0.f, 0.f, 0.f);
            __pipeline_memcpy_async(&Bs[bsel][br][(bslot + j) * 4],
                                    Bw + (size_t)(k0 + br) * N + nBase + (bslot + j) * 4, 16);
        }
    };

    issue(0, 0); __pipeline_commit();
    issue(1, 1); __pipeline_commit();

    for (int kt = 0; kt < NT; kt++) {
        int cur = kt % 3;
        if (kt + 1 < NT) __pipeline_wait_prior(1);
        else             __pipeline_wait_prior(0);
        __syncthreads();
        if (kt + 2 < NT) {
            issue(kt + 2, (kt + 2) % 3);
            __pipeline_commit();
        }
        #pragma unroll
        for (int ks = 0; ks < 4; ks++) {
            wmma::fragment<wmma::matrix_a, 16, 16, 8, wmma::precision::tf32, wmma::row_major> af[4];
            wmma::fragment<wmma::matrix_b, 16, 16, 8, wmma::precision::tf32, wmma::row_major> bf[2];
            #pragma unroll
            for (int mi = 0; mi < 4; mi++)
                wmma::load_matrix_sync(af[mi], &As[cur][warp_m * 64 + mi * 16][ks * 8], ALD);
            #pragma unroll
            for (int ni = 0; ni < 2; ni++)
                wmma::load_matrix_sync(bf[ni], &Bs[cur][ks * 8][warp_n * 32 + ni * 16], BLD);
            #pragma unroll
            for (int mi = 0; mi < 4; mi++)
                #pragma unroll
                for (int ni = 0; ni < 2; ni++)
                    wmma::mma_sync(cf[mi][ni], af[mi], bf[ni], cf[mi][ni]);
        }
        __syncthreads();
    }

    #pragma unroll
    for (int mi = 0; mi < 4; mi++) {
        int row = mBase + warp_m * 64 + mi * 16;
        if (row >= M) continue;
        #pragma unroll
        for (int ni = 0; ni < 2; ni++) {
            int col = nBase + warp_n * 32 + ni * 16;
            wmma::store_matrix_sync(C + (size_t)row * N + col, cf[mi][ni], N, wmma::mem_row_major);
        }
    }
}

// Fused Cheb GEMM: out = celu([Tx0|Tx1|Tx2] @ tf32(Wc) + bc)
// K-tiles (32 wide): 0-15 = bufB(Tx0), 16-31 = bufA(Tx1), 32-47 = bufC(Tx2).
__global__ void __launch_bounds__(256, 2)
k_cgemm(const float* __restrict__ bias, float* __restrict__ C) {
    constexpr int M = NNODES, N = DOUT;
    constexpr int NT = 48;

    const float* Bw = g_wc;

    extern __shared__ float dsm[];
    float (*As)[128][ALD] = (float(*)[128][ALD])dsm;
    float (*Bs)[32][BLD]  = (float(*)[32][BLD])(dsm + AS_ELEMS);

    int tid = threadIdx.x;
    int lane = tid & 31;
    int wid = tid >> 5;
    int warp_m = wid >> 2;
    int warp_n = wid & 3;
    int mBase = blockIdx.x * 128;
    int nBase = blockIdx.y * 128;

    wmma::fragment<wmma::accumulator, 16, 16, 8, float> cf[4][2];
    #pragma unroll
    for (int mi = 0; mi < 4; mi++)
        #pragma unroll
        for (int ni = 0; ni < 2; ni++)
            wmma::fill_fragment(cf[mi][ni], 0.0f);

    int ar = tid >> 1;
    int aslot = (tid & 1) * 4;
    int br = tid >> 3;
    int bslot = (tid & 7) * 4;

    bool aValid = (mBase + ar) < M;

    auto issue = [&](int kt, int bsel) {
        const float* A = (kt < 16) ? g_bufB : (kt < 32) ? g_bufA : g_bufC;
        int k0 = (kt & 15) * 32;
        const float* aRowPtr = A + (size_t)(mBase + ar) * DFEAT;
        #pragma unroll
        for (int j = 0; j < 4; j++) {
            if (aValid)
                __pipeline_memcpy_async(&As[bsel][ar][(aslot + j) * 4],
                                        aRowPtr + k0 + (aslot + j) * 4, 16);
            else
                *(float4*)&As[bsel][ar][(aslot + j) * 4] = make_float4(0.f, 0.f, 0.f, 0.f);
            __pipeline_memcpy_async(&Bs[bsel][br][(bslot + j) * 4],
                                    Bw + (size_t)(kt * 32 + br) * N + nBase + (bslot + j) * 4, 16);
        }
    };

    issue(0, 0); __pipeline_commit();
    issue(1, 1); __pipeline_commit();

    for (int kt = 0; kt < NT; kt++) {
        int cur = kt % 3;
        if (kt + 1 < NT) __pipeline_wait_prior(1);
        else             __pipeline_wait_prior(0);
        __syncthreads();
        if (kt + 2 < NT) {
            issue(kt + 2, (kt + 2) % 3);
            __pipeline_commit();
        }
        #pragma unroll
        for (int ks = 0; ks < 4; ks++) {
            wmma::fragment<wmma::matrix_a, 16, 16, 8, wmma::precision::tf32, wmma::row_major> af[4];
            wmma::fragment<wmma::matrix_b, 16, 16, 8, wmma::precision::tf32, wmma::row_major> bf[2];
            #pragma unroll
            for (int mi = 0; mi < 4; mi++)
                wmma::load_matrix_sync(af[mi], &As[cur][warp_m * 64 + mi * 16][ks * 8], ALD);
            #pragma unroll
            for (int ni = 0; ni < 2; ni++)
                wmma::load_matrix_sync(bf[ni], &Bs[cur][ks * 8][warp_n * 32 + ni * 16], BLD);
            #pragma unroll
            for (int mi = 0; mi < 4; mi++)
                #pragma unroll
                for (int ni = 0; ni < 2; ni++)
                    wmma::mma_sync(cf[mi][ni], af[mi], bf[ni], cf[mi][ni]);
        }
        __syncthreads();
    }

    // epilogue: bias + celu via per-warp staging overlaid on pipeline smem (now dead)
    __syncthreads();
    float (*stage)[16][SLD] = (float(*)[16][SLD])dsm;
    int sr = lane >> 1;
    int sc = (lane & 1) * 8;
    #pragma unroll
    for (int mi = 0; mi < 4; mi++) {
        int rowBase = mBase + warp_m * 64 + mi * 16;
        #pragma unroll
        for (int ni = 0; ni < 2; ni++) {
            int colBase = nBase + warp_n * 32 + ni * 16;
            wmma::store_matrix_sync(&stage[wid][0][0], cf[mi][ni], SLD, wmma::mem_row_major);
            __syncwarp();
            int row = rowBase + sr;
            if (row < M) {
                float* cp = C + (size_t)row * N + colBase + sc;
                #pragma unroll
                for (int j = 0; j < 8; j++) {
                    float v = stage[wid][sr][sc + j] + bias[colBase + sc + j];
                    cp[j] = celuf(v);
                }
            }
            __syncwarp();
        }
    }
}

// ---------------- launch ----------------
extern "C" void kernel_launch(void* const* d_in, const int* in_sizes, int n_in,
                              void* d_out, int out_size) {
    const float* x  = (const float*)d_in[0];
    const int*   ei = (const int*)d_in[1];
    const float* w  = (const float*)d_in[2];
    const float* W1 = (const float*)d_in[3];
    const float* b1 = (const float*)d_in[4];
    const float* W2 = (const float*)d_in[5];
    const float* b2 = (const float*)d_in[6];
    const float* Wc = (const float*)d_in[7];
    const float* bc = (const float*)d_in[8];
    float* out = (float*)d_out;

    setup_attrs();   // idempotent; non-stream host call, safe under capture

    // edge preprocessing + dest-CSR build
    k_init  <<<(NNODES + 255) / 256, 256>>>(ei);
    k_edge1 <<<(NEDGES + 255) / 256, 256>>>(ei, w);
    k_scan  <<<1, 1024>>>();
    k_dinv  <<<(NNODES + 255) / 256, 256>>>();
    k_edge2 <<<(NEDGES + 255) / 256, 256>>>(w);

    // tf32 pre-conversions (x -> bufC, W1/W2 -> g_w12, Wc -> g_wc)
    const int TOT4 = XN4 + 2 * WN4 + CN4;
    k_cvtall<<<(TOT4 + 255) / 256, 256>>>(x, W1, W2, Wc);

    dim3 blk(256);
    dim3 g512((NNODES + 127) / 128, 4);
    dim3 g256((NNODES + 127) / 128, 2);

    // GCN layer 1: bufA = tf32(x)@W1 ; bufB = tf32(celu(spmm(bufA)+self+b1))
    k_tgemm<2, 0><<<g512, blk, SMEM_DYN>>>();
    k_spmm<0, 0, 1, 0><<<NNODES, 128>>>(b1);

    // GCN layer 2: bufA = bufB@W2 ; bufB = ...
    k_tgemm<1, DFEAT * DFEAT><<<g512, blk, SMEM_DYN>>>();
    k_spmm<0, 0, 1, 0><<<NNODES, 128>>>(b2);

    // Cheb: Tx0 = bufB; Tx1 = bufA; Tx2 = bufC; fused GEMM w/ bias+celu epilogue
    k_spmm<1, 1, 0, 0><<<NNODES, 128>>>(nullptr);   // bufA = Tx1 = lhat(Tx0)
    k_spmm<2, 0, 2, 1><<<NNODES, 128>>>(nullptr);   // bufC = Tx2 = 2*lhat(Tx1) - Tx0
    k_cgemm<<<g256, blk, SMEM_DYN>>>(bc, out);
}